// round 6
// baseline (speedup 1.0000x reference)
#include <cuda_runtime.h>

// CollisionLoss — single fused kernel, R4 body (coalesced item-per-thread,
// unroll-4 strided) + last-block-done reduction (kills memset + extra sync).
//
//  d_in[0] sdc_traj_all        (1, F, 2) f32
//  d_in[1] sdc_planning_gt     (1, F, 3) f32  (theta = [...,2])
//  d_in[2] sdc_planning_gt_mask (unused)
//  d_in[3] future_gt_corners   (F, N, 4, 2) f32  [192 MB]
//  d_in[4] box_mask            (F, N) bool as int32 [24 MB]
// output: 1 x f32

#define F_FRAMES 6
#define N_PTS    1000000u
#define TOTAL    (F_FRAMES * N_PTS)
#define W_BOX    2.35f
#define H_BOX    4.584f

#define NTHREADS 256
#define NBLOCKS  2368                  /* 148 SMs * 16 */
#define UNROLL   4

__device__ float    g_partial[NBLOCKS];   // overwritten every launch
__device__ unsigned g_count = 0;          // atomicInc wraps back to 0 -> deterministic

__device__ __forceinline__ float4 ldcs4(const float4* p) {
    float4 v;
    asm volatile("ld.global.cs.v4.f32 {%0,%1,%2,%3}, [%4];"
                 : "=f"(v.x), "=f"(v.y), "=f"(v.z), "=f"(v.w) : "l"(p));
    return v;
}
__device__ __forceinline__ int ldcsi(const int* p) {
    int v;
    asm volatile("ld.global.cs.b32 %0, [%1];" : "=r"(v) : "l"(p));
    return v;
}

__global__ __launch_bounds__(NTHREADS)
void collision_fused_kernel(const float* __restrict__ traj,
                            const float* __restrict__ gt,
                            const float4* __restrict__ corners,
                            const int* __restrict__ mask,
                            float* __restrict__ out)
{
    __shared__ float4 sbox[F_FRAMES];   // (xmax, ymax, xmin, ymin)
    if (threadIdx.x < F_FRAMES) {
        int f = threadIdx.x;
        float x  = traj[f * 2 + 0];
        float y  = traj[f * 2 + 1];
        float th = gt[f * 3 + 2];
        float c, s;
        __sincosf(th, &s, &c);
        const float hw = W_BOX * 0.5f, hh = H_BOX * 0.5f;
        const float lx[4] = { hw,  hw, -hw, -hw };
        const float ly[4] = {-hh,  hh,  hh, -hh };
        float xmax = -1e30f, xmin = 1e30f, ymax = -1e30f, ymin = 1e30f;
#pragma unroll
        for (int k = 0; k < 4; k++) {
            float cx =  c * lx[k] + s * ly[k] + x;   // rot = [[c,s],[-s,c]]
            float cy = -s * lx[k] + c * ly[k] + y;
            xmax = fmaxf(xmax, cx); xmin = fminf(xmin, cx);
            ymax = fmaxf(ymax, cy); ymin = fminf(ymin, cy);
        }
        sbox[f] = make_float4(xmax, ymax, xmin, ymin);
    }
    __syncthreads();

    const unsigned stride = gridDim.x * blockDim.x;        // 606,208
    const unsigned tid0   = blockIdx.x * blockDim.x + threadIdx.x;

    float acc = 0.0f;
    for (unsigned base = tid0; base < TOTAL; base += stride * UNROLL) {
        unsigned items[UNROLL];
        bool     ok[UNROLL];
        float4   c0[UNROLL], c1[UNROLL];
        int      m[UNROLL];
#pragma unroll
        for (int k = 0; k < UNROLL; k++) {
            items[k] = base + (unsigned)k * stride;
            ok[k] = items[k] < TOTAL;
            unsigned it = ok[k] ? items[k] : 0u;
            c0[k] = ldcs4(&corners[(size_t)it * 2u + 0u]);
            c1[k] = ldcs4(&corners[(size_t)it * 2u + 1u]);
            m[k]  = ldcsi(&mask[it]);
        }
#pragma unroll
        for (int k = 0; k < UNROLL; k++) {
            unsigned f = items[k] / N_PTS;
            float4 b = sbox[ok[k] ? f : 0u];
            float xb1 = fmaxf(fmaxf(c0[k].x, c0[k].z), fmaxf(c1[k].x, c1[k].z));
            float xb2 = fminf(fminf(c0[k].x, c0[k].z), fminf(c1[k].x, c1[k].z));
            float yb1 = fmaxf(fmaxf(c0[k].y, c0[k].w), fmaxf(c1[k].y, c1[k].w));
            float yb2 = fminf(fminf(c0[k].y, c0[k].w), fminf(c1[k].y, c1[k].w));
            float w = fmaxf(0.0f, fminf(b.x, xb1) - fmaxf(b.z, xb2));
            float h = fmaxf(0.0f, fminf(b.y, yb1) - fmaxf(b.w, yb2));
            acc += (ok[k] && m[k]) ? (w * h) : 0.0f;
        }
    }

    // block reduce
#pragma unroll
    for (int o = 16; o > 0; o >>= 1)
        acc += __shfl_down_sync(0xffffffffu, acc, o);

    __shared__ float ws[NTHREADS / 32];
    __shared__ bool  s_last;
    if ((threadIdx.x & 31) == 0) ws[threadIdx.x >> 5] = acc;
    __syncthreads();
    if (threadIdx.x == 0) {
        float v = 0.0f;
#pragma unroll
        for (int i = 0; i < NTHREADS / 32; i++) v += ws[i];
        g_partial[blockIdx.x] = v;
        __threadfence();
        unsigned prev = atomicInc(&g_count, NBLOCKS - 1u);  // wraps to 0 on last
        s_last = (prev == NBLOCKS - 1u);
    }
    __syncthreads();

    if (s_last) {
        // last block: reduce all partials, write scalar
        float v = 0.0f;
        for (int i = threadIdx.x; i < NBLOCKS; i += NTHREADS)
            v += g_partial[i];
#pragma unroll
        for (int o = 16; o > 0; o >>= 1)
            v += __shfl_down_sync(0xffffffffu, v, o);
        if ((threadIdx.x & 31) == 0) ws[threadIdx.x >> 5] = v;
        __syncthreads();
        if (threadIdx.x == 0) {
            float t = 0.0f;
#pragma unroll
            for (int i = 0; i < NTHREADS / 32; i++) t += ws[i];
            out[0] = t;   // WEIGHT = 1.0
        }
    }
}

extern "C" void kernel_launch(void* const* d_in, const int* in_sizes, int n_in,
                              void* d_out, int out_size)
{
    const float* traj = (const float*)d_in[0];
    const float* gt   = (const float*)d_in[1];
    const float4* corners = (const float4*)d_in[3];
    const int* mask = (const int*)d_in[4];
    float* out = (float*)d_out;

    collision_fused_kernel<<<NBLOCKS, NTHREADS>>>(traj, gt, corners, mask, out);
}

// round 7
// speedup vs baseline: 1.1674x; 1.1674x over previous
#include <cuda_runtime.h>

// CollisionLoss — R4 structure (memset node + fused kernel + atomicAdd finish,
// coalesced item-per-thread strided loads) with UNROLL raised 4 -> 6 for
// deeper MLP. R6 post-mortem: last-block-done reduction added a serialized
// memory-idle tail (+5.6us kernel) — memset node is cheaper; reverted.
//
//  d_in[0] sdc_traj_all        (1, F, 2) f32
//  d_in[1] sdc_planning_gt     (1, F, 3) f32  (theta = [...,2])
//  d_in[2] sdc_planning_gt_mask (unused)
//  d_in[3] future_gt_corners   (F, N, 4, 2) f32  [192 MB]
//  d_in[4] box_mask            (F, N) bool as int32 [24 MB]
// output: 1 x f32

#define F_FRAMES 6
#define N_PTS    1000000u
#define TOTAL    (F_FRAMES * N_PTS)
#define W_BOX    2.35f
#define H_BOX    4.584f

#define NTHREADS 256
#define NBLOCKS  2368                  /* 148 SMs * 16 */
#define UNROLL   6

__device__ __forceinline__ float4 ldcs4(const float4* p) {
    float4 v;
    asm volatile("ld.global.cs.v4.f32 {%0,%1,%2,%3}, [%4];"
                 : "=f"(v.x), "=f"(v.y), "=f"(v.z), "=f"(v.w) : "l"(p));
    return v;
}
__device__ __forceinline__ int ldcsi(const int* p) {
    int v;
    asm volatile("ld.global.cs.b32 %0, [%1];" : "=r"(v) : "l"(p));
    return v;
}

__global__ __launch_bounds__(NTHREADS, 3)
void collision_fused_kernel(const float* __restrict__ traj,
                            const float* __restrict__ gt,
                            const float4* __restrict__ corners,
                            const int* __restrict__ mask,
                            float* __restrict__ out)
{
    __shared__ float4 sbox[F_FRAMES];   // (xmax, ymax, xmin, ymin)
    if (threadIdx.x < F_FRAMES) {
        int f = threadIdx.x;
        float x  = traj[f * 2 + 0];
        float y  = traj[f * 2 + 1];
        float th = gt[f * 3 + 2];
        float c, s;
        __sincosf(th, &s, &c);
        const float hw = W_BOX * 0.5f, hh = H_BOX * 0.5f;
        const float lx[4] = { hw,  hw, -hw, -hw };
        const float ly[4] = {-hh,  hh,  hh, -hh };
        float xmax = -1e30f, xmin = 1e30f, ymax = -1e30f, ymin = 1e30f;
#pragma unroll
        for (int k = 0; k < 4; k++) {
            float cx =  c * lx[k] + s * ly[k] + x;   // rot = [[c,s],[-s,c]]
            float cy = -s * lx[k] + c * ly[k] + y;
            xmax = fmaxf(xmax, cx); xmin = fminf(xmin, cx);
            ymax = fmaxf(ymax, cy); ymin = fminf(ymin, cy);
        }
        sbox[f] = make_float4(xmax, ymax, xmin, ymin);
    }
    __syncthreads();

    const unsigned stride = gridDim.x * blockDim.x;        // 606,208
    const unsigned tid0   = blockIdx.x * blockDim.x + threadIdx.x;

    float acc = 0.0f;
    for (unsigned base = tid0; base < TOTAL; base += stride * UNROLL) {
        unsigned items[UNROLL];
        bool     ok[UNROLL];
        float4   c0[UNROLL], c1[UNROLL];
        int      m[UNROLL];
#pragma unroll
        for (int k = 0; k < UNROLL; k++) {
            items[k] = base + (unsigned)k * stride;
            ok[k] = items[k] < TOTAL;
            unsigned it = ok[k] ? items[k] : 0u;
            c0[k] = ldcs4(&corners[(size_t)it * 2u + 0u]);
            c1[k] = ldcs4(&corners[(size_t)it * 2u + 1u]);
            m[k]  = ldcsi(&mask[it]);
        }
#pragma unroll
        for (int k = 0; k < UNROLL; k++) {
            unsigned f = items[k] / N_PTS;
            float4 b = sbox[ok[k] ? f : 0u];
            float xb1 = fmaxf(fmaxf(c0[k].x, c0[k].z), fmaxf(c1[k].x, c1[k].z));
            float xb2 = fminf(fminf(c0[k].x, c0[k].z), fminf(c1[k].x, c1[k].z));
            float yb1 = fmaxf(fmaxf(c0[k].y, c0[k].w), fmaxf(c1[k].y, c1[k].w));
            float yb2 = fminf(fminf(c0[k].y, c0[k].w), fminf(c1[k].y, c1[k].w));
            float w = fmaxf(0.0f, fminf(b.x, xb1) - fmaxf(b.z, xb2));
            float h = fmaxf(0.0f, fminf(b.y, yb1) - fmaxf(b.w, yb2));
            acc += (ok[k] && m[k]) ? (w * h) : 0.0f;
        }
    }

    // warp reduce
#pragma unroll
    for (int o = 16; o > 0; o >>= 1)
        acc += __shfl_down_sync(0xffffffffu, acc, o);

    __shared__ float ws[NTHREADS / 32];
    if ((threadIdx.x & 31) == 0) ws[threadIdx.x >> 5] = acc;
    __syncthreads();
    if (threadIdx.x == 0) {
        float v = 0.0f;
#pragma unroll
        for (int i = 0; i < NTHREADS / 32; i++) v += ws[i];
        atomicAdd(out, v);   // WEIGHT = 1.0 ; lowers to REDG (no return)
    }
}

extern "C" void kernel_launch(void* const* d_in, const int* in_sizes, int n_in,
                              void* d_out, int out_size)
{
    const float* traj = (const float*)d_in[0];
    const float* gt   = (const float*)d_in[1];
    const float4* corners = (const float4*)d_in[3];
    const int* mask = (const int*)d_in[4];
    float* out = (float*)d_out;

    cudaMemsetAsync(out, 0, sizeof(float));
    collision_fused_kernel<<<NBLOCKS, NTHREADS>>>(traj, gt, corners, mask, out);
}